// round 14
// baseline (speedup 1.0000x reference)
#include <cuda_runtime.h>
#include <cstdint>

// QuantizedKVCache_52381421142177 — R14: winner with default (evict-normal)
// output stores. Last untested cell of the store-policy axis.
//
// Fixed shapes:
//   k_val/v_val    : (1, 128, 32, 128)  f32
//   k_cache/v_cache: (1, 8192, 32, 128) i32
//   k_scales/v_scales: (1, 8192, 32, 1) f32
//   k_zp/v_zp      : (1, 8192, 32, 1) i32
//   input_pos      : scalar i32
// Output: concat(k_out, v_out), each (1, 8192, 32, 128) f32.
//
// Output semantics (fresh-token quantization is dead code w.r.t. output):
//   s in [pos, pos+128):  out = val (exact fp copy)
//   else:                 out = (q - zp)*scale == q*sc + (-zp*sc)  (one FFMA)
//
// Store-policy axis: __stwt (eager DRAM writes) measured WORSE (+1.4us),
// __stcs (evict-first) is the 6x-reproduced baseline. Theory here: plain
// evict-normal stores let dirty lines age in L2 so the memory controller
// drains writebacks in longer batched bursts with fewer read<->write bus
// turnarounds (the source of the ~20% DRAM idle). Reads stay __ldcs
// (single-use; L2 pollution by dirty lines costs nothing). Prediction:
// either ~-2us kernel (write batching real) or neutral (MC batches anyway).

static constexpr int S_MAX    = 8192;
static constexpr int S_NEW    = 128;
static constexpr int V4_PER_S = 1024;          // 32 heads * 32 vec4
static constexpr int T_PER_S  = 32;            // token rows per seq pos
static constexpr int N_BLOCKS = S_MAX;         // 2 caches * 4096 seq-pairs

__device__ __forceinline__ void copy_fresh(const float4* __restrict__ val,
                                           float4* __restrict__ dst,
                                           unsigned tid)
{
    #pragma unroll
    for (int k = 0; k < 4; k++) {
        const unsigned e = k * 256 + tid;
        dst[e] = __ldcs(val + e);
    }
}

__device__ __forceinline__ void dequant_one(const int4* __restrict__ cache,
                                            const float* __restrict__ scales,
                                            const int* __restrict__ zps,
                                            float4* __restrict__ dst,
                                            unsigned tid)
{
    int4  q[4];
    float sc[4], nzpsc[4];
    #pragma unroll
    for (int k = 0; k < 4; k++) {
        const unsigned e = k * 256 + tid;
        q[k] = __ldcs(cache + e);
        const unsigned trow = e >> 5;
        sc[k] = __ldg(scales + trow);
        nzpsc[k] = -(float)__ldg(zps + trow) * sc[k];
    }
    #pragma unroll
    for (int k = 0; k < 4; k++) {
        const unsigned e = k * 256 + tid;
        float4 r;
        r.x = fmaf((float)q[k].x, sc[k], nzpsc[k]);
        r.y = fmaf((float)q[k].y, sc[k], nzpsc[k]);
        r.z = fmaf((float)q[k].z, sc[k], nzpsc[k]);
        r.w = fmaf((float)q[k].w, sc[k], nzpsc[k]);
        dst[e] = r;
    }
}

__global__ void __launch_bounds__(256)
qkv_dequant_kernel(const float4* __restrict__ k_val,
                   const float4* __restrict__ v_val,
                   const int4*   __restrict__ k_cache,
                   const int4*   __restrict__ v_cache,
                   const float*  __restrict__ k_scales,
                   const float*  __restrict__ v_scales,
                   const int*    __restrict__ k_zp,
                   const int*    __restrict__ v_zp,
                   const int*    __restrict__ pos_ptr,
                   float4*       __restrict__ out)
{
    const unsigned bid  = blockIdx.x;            // [0, 8192)
    const unsigned is_v = bid >> 12;             // 0 = K, 1 = V (uniform)
    const unsigned s0   = (bid & 4095) << 1;     // first seq position of pair
    const unsigned tid  = threadIdx.x;

    const unsigned pos = (unsigned)*pos_ptr;
    const unsigned sl0 = s0 - pos;               // fresh iff < S_NEW
    const unsigned sl1 = s0 + 1 - pos;
    const bool fresh0 = sl0 < (unsigned)S_NEW;
    const bool fresh1 = sl1 < (unsigned)S_NEW;

    const unsigned jbase = s0 * V4_PER_S;
    float4* dst = out + (size_t)is_v * ((size_t)S_MAX * V4_PER_S) + jbase;

    const int4*  cache  = (is_v ? v_cache  : k_cache)  + jbase;
    const float* scales = (is_v ? v_scales : k_scales) + s0 * T_PER_S;
    const int*   zps    = (is_v ? v_zp     : k_zp)     + s0 * T_PER_S;

    if (!fresh0 && !fresh1) {
        // ---- hot path: both stale, 8 front-batched loads (MLP=8) ----
        int4  q[8];
        float sc[8], nzpsc[8];
        #pragma unroll
        for (int k = 0; k < 8; k++) {
            const unsigned e = k * 256 + tid;
            q[k] = __ldcs(cache + e);
            const unsigned trow = e >> 5;
            sc[k] = __ldg(scales + trow);
            nzpsc[k] = -(float)__ldg(zps + trow) * sc[k];
        }
        #pragma unroll
        for (int k = 0; k < 8; k++) {
            const unsigned e = k * 256 + tid;
            float4 r;
            r.x = fmaf((float)q[k].x, sc[k], nzpsc[k]);
            r.y = fmaf((float)q[k].y, sc[k], nzpsc[k]);
            r.z = fmaf((float)q[k].z, sc[k], nzpsc[k]);
            r.w = fmaf((float)q[k].w, sc[k], nzpsc[k]);
            dst[e] = r;
        }
    } else {
        // ---- rare path (fresh region boundary): per-sub-tile handling ----
        const float4* valbase = is_v ? v_val : k_val;
        if (fresh0) copy_fresh(valbase + (size_t)sl0 * V4_PER_S, dst, tid);
        else        dequant_one(cache, scales, zps, dst, tid);

        if (fresh1) copy_fresh(valbase + (size_t)sl1 * V4_PER_S,
                               dst + V4_PER_S, tid);
        else        dequant_one(cache + V4_PER_S, scales + T_PER_S,
                                zps + T_PER_S, dst + V4_PER_S, tid);
    }
}

extern "C" void kernel_launch(void* const* d_in, const int* in_sizes, int n_in,
                              void* d_out, int out_size)
{
    const float4* k_val    = (const float4*)d_in[0];
    const float4* v_val    = (const float4*)d_in[1];
    const int4*   k_cache  = (const int4*)d_in[2];
    const int4*   v_cache  = (const int4*)d_in[3];
    const float*  k_scales = (const float*)d_in[4];
    const float*  v_scales = (const float*)d_in[5];
    const int*    k_zp     = (const int*)d_in[6];
    const int*    v_zp     = (const int*)d_in[7];
    const int*    pos_ptr  = (const int*)d_in[8];

    qkv_dequant_kernel<<<N_BLOCKS, 256>>>(
        k_val, v_val, k_cache, v_cache,
        k_scales, v_scales, k_zp, v_zp,
        pos_ptr, (float4*)d_out);
}

// round 15
// speedup vs baseline: 1.0246x; 1.0246x over previous
#include <cuda_runtime.h>
#include <cstdint>

// QuantizedKVCache_52381421142177 — FINAL (6x-reproduced winner, unchanged).
//
// Fixed shapes:
//   k_val/v_val    : (1, 128, 32, 128)  f32
//   k_cache/v_cache: (1, 8192, 32, 128) i32
//   k_scales/v_scales: (1, 8192, 32, 1) f32
//   k_zp/v_zp      : (1, 8192, 32, 1) i32
//   input_pos      : scalar i32
// Output: concat(k_out, v_out), each (1, 8192, 32, 128) f32.
//
// Output semantics (fresh-token quantization is dead code w.r.t. output):
//   s in [pos, pos+128):  out = val (exact fp copy)
//   else:                 out = (q - zp)*scale == q*sc + (-zp*sc)  (one FFMA)
//
// Roofline closure (12 measurements, R2-R14): 6.26-6.40 TB/s invariant
// under occupancy 42-86%, MLP 4-8, five grid shapes, and the COMPLETE
// load/store policy matrix -> HBM mixed read/write ceiling (~80%
// bus-active) on the mandatory ~536 MB (268 MB int32 cache reads + 268 MB
// f32 output writes; formats fixed by the problem, fresh-region cache
// reads elided). Residual ~20% DRAM idle = read<->write bus turnaround,
// workload-intrinsic. Falsified: persistent grids (-12%), wave-transition
// loss, K/V interleaving, __stwt (+2us), plain stores (+2us), inter-replay
// L2 retention (+1.8us).
//
// Design (best measured: 81.98-82.05us harness; 75.84us kernel):
//   - one block = one (cache, seq-pair) tile of 2048 vec4
//   - fresh/stale branch block-uniform, 32-bit uniform indexing
//   - hot path front-batches 8 int4 loads per thread (MLP=8)
//   - dequant folded to a single FFMA per element
//   - __ldcs loads + __stcs stores (measured-optimal policy pair)

static constexpr int S_MAX    = 8192;
static constexpr int S_NEW    = 128;
static constexpr int V4_PER_S = 1024;          // 32 heads * 32 vec4
static constexpr int T_PER_S  = 32;            // token rows per seq pos
static constexpr int N_BLOCKS = S_MAX;         // 2 caches * 4096 seq-pairs

__device__ __forceinline__ void copy_fresh(const float4* __restrict__ val,
                                           float4* __restrict__ dst,
                                           unsigned tid)
{
    #pragma unroll
    for (int k = 0; k < 4; k++) {
        const unsigned e = k * 256 + tid;
        __stcs(dst + e, __ldcs(val + e));
    }
}

__device__ __forceinline__ void dequant_one(const int4* __restrict__ cache,
                                            const float* __restrict__ scales,
                                            const int* __restrict__ zps,
                                            float4* __restrict__ dst,
                                            unsigned tid)
{
    int4  q[4];
    float sc[4], nzpsc[4];
    #pragma unroll
    for (int k = 0; k < 4; k++) {
        const unsigned e = k * 256 + tid;
        q[k] = __ldcs(cache + e);
        const unsigned trow = e >> 5;
        sc[k] = __ldg(scales + trow);
        nzpsc[k] = -(float)__ldg(zps + trow) * sc[k];
    }
    #pragma unroll
    for (int k = 0; k < 4; k++) {
        const unsigned e = k * 256 + tid;
        float4 r;
        r.x = fmaf((float)q[k].x, sc[k], nzpsc[k]);
        r.y = fmaf((float)q[k].y, sc[k], nzpsc[k]);
        r.z = fmaf((float)q[k].z, sc[k], nzpsc[k]);
        r.w = fmaf((float)q[k].w, sc[k], nzpsc[k]);
        __stcs(dst + e, r);
    }
}

__global__ void __launch_bounds__(256)
qkv_dequant_kernel(const float4* __restrict__ k_val,
                   const float4* __restrict__ v_val,
                   const int4*   __restrict__ k_cache,
                   const int4*   __restrict__ v_cache,
                   const float*  __restrict__ k_scales,
                   const float*  __restrict__ v_scales,
                   const int*    __restrict__ k_zp,
                   const int*    __restrict__ v_zp,
                   const int*    __restrict__ pos_ptr,
                   float4*       __restrict__ out)
{
    const unsigned bid  = blockIdx.x;            // [0, 8192)
    const unsigned is_v = bid >> 12;             // 0 = K, 1 = V (uniform)
    const unsigned s0   = (bid & 4095) << 1;     // first seq position of pair
    const unsigned tid  = threadIdx.x;

    const unsigned pos = (unsigned)*pos_ptr;
    const unsigned sl0 = s0 - pos;               // fresh iff < S_NEW
    const unsigned sl1 = s0 + 1 - pos;
    const bool fresh0 = sl0 < (unsigned)S_NEW;
    const bool fresh1 = sl1 < (unsigned)S_NEW;

    const unsigned jbase = s0 * V4_PER_S;
    float4* dst = out + (size_t)is_v * ((size_t)S_MAX * V4_PER_S) + jbase;

    const int4*  cache  = (is_v ? v_cache  : k_cache)  + jbase;
    const float* scales = (is_v ? v_scales : k_scales) + s0 * T_PER_S;
    const int*   zps    = (is_v ? v_zp     : k_zp)     + s0 * T_PER_S;

    if (!fresh0 && !fresh1) {
        // ---- hot path: both stale, 8 front-batched loads (MLP=8) ----
        int4  q[8];
        float sc[8], nzpsc[8];
        #pragma unroll
        for (int k = 0; k < 8; k++) {
            const unsigned e = k * 256 + tid;
            q[k] = __ldcs(cache + e);
            const unsigned trow = e >> 5;
            sc[k] = __ldg(scales + trow);
            nzpsc[k] = -(float)__ldg(zps + trow) * sc[k];
        }
        #pragma unroll
        for (int k = 0; k < 8; k++) {
            const unsigned e = k * 256 + tid;
            float4 r;
            r.x = fmaf((float)q[k].x, sc[k], nzpsc[k]);
            r.y = fmaf((float)q[k].y, sc[k], nzpsc[k]);
            r.z = fmaf((float)q[k].z, sc[k], nzpsc[k]);
            r.w = fmaf((float)q[k].w, sc[k], nzpsc[k]);
            __stcs(dst + e, r);
        }
    } else {
        // ---- rare path (fresh region boundary): per-sub-tile handling ----
        const float4* valbase = is_v ? v_val : k_val;
        if (fresh0) copy_fresh(valbase + (size_t)sl0 * V4_PER_S, dst, tid);
        else        dequant_one(cache, scales, zps, dst, tid);

        if (fresh1) copy_fresh(valbase + (size_t)sl1 * V4_PER_S,
                               dst + V4_PER_S, tid);
        else        dequant_one(cache + V4_PER_S, scales + T_PER_S,
                                zps + T_PER_S, dst + V4_PER_S, tid);
    }
}

extern "C" void kernel_launch(void* const* d_in, const int* in_sizes, int n_in,
                              void* d_out, int out_size)
{
    const float4* k_val    = (const float4*)d_in[0];
    const float4* v_val    = (const float4*)d_in[1];
    const int4*   k_cache  = (const int4*)d_in[2];
    const int4*   v_cache  = (const int4*)d_in[3];
    const float*  k_scales = (const float*)d_in[4];
    const float*  v_scales = (const float*)d_in[5];
    const int*    k_zp     = (const int*)d_in[6];
    const int*    v_zp     = (const int*)d_in[7];
    const int*    pos_ptr  = (const int*)d_in[8];

    qkv_dequant_kernel<<<N_BLOCKS, 256>>>(
        k_val, v_val, k_cache, v_cache,
        k_scales, v_scales, k_zp, v_zp,
        pos_ptr, (float4*)d_out);
}